// round 6
// baseline (speedup 1.0000x reference)
#include <cuda_runtime.h>

#define NBOX 16384
#define NW   256            // 64-bit words per mask row
#define NBKT 16384          // conf buckets for counting sort
#define CONF_THRESH 0.5f
#define PIOU_THRESH 0.5f

typedef unsigned long long u64;

// ---------------- device scratch (static; no allocation) ----------------
__device__ float4 g_seph[NBOX];                    // sorted [start,end,peak,height]
__device__ float  g_conf[NBOX];                    // dense confidence (unsorted)
__device__ int    g_hist[NBKT];                    // bucket histogram
__device__ int    g_off[NBKT];                     // #elements in buckets > b
__device__ int    g_cnt[NBKT];                     // scatter cursors
__device__ int    g_blist[NBOX];                   // bucket-grouped original indices
__device__ int    g_M;                             // count(conf > 0.5) == valid prefix len
__device__ u64    g_mask[(size_t)NBOX * NW];       // 32MB suppression bitmask
__device__ u64    g_keep[NW];                      // final keep bits (sorted order)

__device__ __forceinline__ int bucket_of(float c) {
    int b = (int)(c * 16384.0f);                   // exact pow2 mul; monotone
    return b > 16383 ? 16383 : b;
}

// ---------------- 1) gather conf, zero accumulators ----------------
__global__ void k_prep(const float* __restrict__ in) {
    int i = blockIdx.x * blockDim.x + threadIdx.x;
    if (i < NBOX) {
        g_conf[i] = in[i * 5 + 0];
        g_hist[i] = 0;
        g_cnt[i]  = 0;
    }
    if (i == 0) g_M = 0;
}

// ---------------- 2a) bucket histogram ----------------
__global__ void k_hist() {
    int i = blockIdx.x * blockDim.x + threadIdx.x;
    if (i < NBOX) atomicAdd(&g_hist[bucket_of(g_conf[i])], 1);
}

// ---------------- 2b) suffix sums: off[b] = #elements with bucket > b ----------
__global__ void k_suffix() {                       // 1 block, 1024 threads
    __shared__ int part[1024];
    int t = threadIdx.x;
    int base = t * 16;
    int v[16]; int s = 0;
#pragma unroll
    for (int k = 0; k < 16; k++) { v[k] = g_hist[base + k]; s += v[k]; }
    part[t] = s;
    __syncthreads();
    for (int off = 1; off < 1024; off <<= 1) {     // inclusive suffix scan of partials
        int x = (t + off < 1024) ? part[t + off] : 0;
        __syncthreads();
        part[t] += x;
        __syncthreads();
    }
    int above = part[t] - s;                       // sum of buckets >= (t+1)*16
    int o[16];
    o[15] = above;
#pragma unroll
    for (int k = 14; k >= 0; k--) o[k] = o[k + 1] + v[k + 1];
#pragma unroll
    for (int k = 0; k < 16; k++) g_off[base + k] = o[k];
}

// ---------------- 2c) scatter indices into bucket segments ----------------
__global__ void k_bscatter() {
    int i = blockIdx.x * blockDim.x + threadIdx.x;
    if (i >= NBOX) return;
    int b = bucket_of(g_conf[i]);
    int pos = g_off[b] + atomicAdd(&g_cnt[b], 1);
    g_blist[pos] = i;
}

// ---------------- 3) exact rank within bucket + scatter boxes ----------------
__global__ void k_rankscatter(const float* __restrict__ in) {
    int i = blockIdx.x * blockDim.x + threadIdx.x;
    if (i >= NBOX) return;
    float ci = g_conf[i];
    int b    = bucket_of(ci);
    int base = g_off[b], len = g_hist[b];
    int cnt = 0;
    for (int p = base; p < base + len; p++) {
        int j = g_blist[p];
        float cj = g_conf[j];
        cnt += (cj > ci) || (cj == ci && j < i);   // stable: (conf desc, idx asc)
    }
    int r = base + cnt;
    const float* row = in + (size_t)i * 5;
    g_seph[r] = make_float4(row[1], row[2], row[3], row[4]);
    if (ci > CONF_THRESH) atomicAdd(&g_M, 1);
}

// ---------------- 4) pairwise peak-IoU bitmask, upper-triangular blocks only ----
__global__ void k_mask() {
    __shared__ float4 cols[64];
    if (blockIdx.x < blockIdx.y) return;           // triangular: halves the work
    int M = g_M;
    if ((int)(blockIdx.y * 64) >= M) return;
    int j0 = blockIdx.x * 64;
    if (j0 >= M) return;
    int r = blockIdx.y * 64 + threadIdx.x;
    cols[threadIdx.x] = g_seph[j0 + threadIdx.x];
    __syncthreads();
    if (r >= M) return;
    float4 a = g_seph[r];
    float area1 = __fmul_rn(__fsub_rn(a.y, a.x), a.w);
    u64 w = 0;
#pragma unroll 4
    for (int k = 0; k < 64; k++) {
        float4 b = cols[k];
        float is = fmaxf(a.x, b.x);
        float ie = fminf(a.y, b.y);
        float il = __fsub_rn(ie, is);
        bool sup = false;
        if (il > 0.0f) {                           // piou>0 requires overlap
            float inter_h    = fminf(a.w, b.w);
            float inter_area = __fmul_rn(il, inter_h);
            float area2      = __fmul_rn(__fsub_rn(b.y, b.x), b.w);
            float union_area = __fsub_rn(__fadd_rn(area1, area2), inter_area);
            float iou        = __fdiv_rn(inter_area, union_area);
            float pd         = fabsf(__fsub_rn(a.z, b.z));
            float us         = fminf(a.x, b.x);
            float ue         = fmaxf(a.y, b.y);
            float ud         = fabsf(__fsub_rn(ue, us));
            float val        = __fsub_rn(iou, __fdiv_rn(pd, ud));
            sup = (val > PIOU_THRESH);
        }
        w |= ((u64)sup) << k;
    }
    int lim = M - j0;                              // mask invalid cols once
    if (lim < 64) w &= (1ULL << lim) - 1ULL;
    if (r >= j0 && r < j0 + 64) w &= ~(1ULL << (r - j0));   // self never suppresses
    g_mask[(size_t)r * NW + blockIdx.x] = w;
}

// ---------------- 5) greedy scan: branchless register chain + split OR gather --
// Single CTA, 256 threads, Mw chunks of 64 rows. Per chunk:
//   (B) thread 0: copy diag to regs, fixed-64 branchless chain (~12cyc/step),
//       build klist, pad to multiple of 16 with klist[0] (OR idempotent)
//   S1; (C) word w handled by 2 threads (w and w+128), each ORs half of klist,
//       merged via shared atomicOr; threads 128..255 also prefetch next diag; S2.
__global__ void __launch_bounds__(256, 1) k_scan() {
    __shared__ u64 remv[NW];
    __shared__ u64 diag[2][64];
    __shared__ int klist[80];
    __shared__ int n16_sh;
    int t = threadIdx.x;
    remv[t] = 0ULL;
    int M  = g_M;
    int Mw = (M + 63) >> 6;
    if (t >= Mw) g_keep[t] = 0ULL;                 // zero unused keep words
    if (t < 64) {                                  // load chunk 0 diag
        diag[0][t] = (t < M) ? g_mask[(size_t)t * NW + 0] : 0ULL;
    }
    __syncthreads();

    for (int c = 0; c < Mw; c++) {
        int buf = c & 1;
        // (B) branchless serial chain in registers
        if (t == 0) {
            u64 d[64];
#pragma unroll
            for (int b = 0; b < 64; b++) d[b] = diag[buf][b];
            int lim = M - (c << 6);
            u64 vmask = (lim >= 64) ? ~0ULL : ((1ULL << lim) - 1ULL);
            u64 rm   = remv[c] | ~vmask;           // invalid slots = pre-removed
            u64 kept = 0ULL;
#pragma unroll
            for (int b = 0; b < 64; b++) {
                u64 m = ((rm >> b) & 1ULL) - 1ULL; // ~0 keep, 0 removed
                kept |= (1ULL << b) & m;
                rm   |= d[b] & m;
            }
            g_keep[c] = kept;
            int n = 0;
            u64 kw = kept;
            int cbase = c << 6;
            while (kw) {
                int b = __ffsll((long long)kw) - 1;
                kw &= kw - 1ULL;
                klist[n++] = cbase + b;
            }
            int n16 = (n + 15) & ~15;              // pad with klist[0] (idempotent)
            for (int p = n; p < n16; p++) klist[p] = klist[0];
            n16_sh = n16;
        }
        __syncthreads();                           // S1: klist/n16 visible
        int n16 = n16_sh;
        // (C) OR kept rows into remv: word w served by threads w and w+128
        if (t < 128) {
            int w = t;
            if (w > c && w < Mw && n16 > 0) {
                int half = n16 >> 1;
                u64 acc = 0ULL;
                for (int i = 0; i < half; i += 8) {
                    u64 v0 = g_mask[(size_t)klist[i + 0] * NW + w];
                    u64 v1 = g_mask[(size_t)klist[i + 1] * NW + w];
                    u64 v2 = g_mask[(size_t)klist[i + 2] * NW + w];
                    u64 v3 = g_mask[(size_t)klist[i + 3] * NW + w];
                    u64 v4 = g_mask[(size_t)klist[i + 4] * NW + w];
                    u64 v5 = g_mask[(size_t)klist[i + 5] * NW + w];
                    u64 v6 = g_mask[(size_t)klist[i + 6] * NW + w];
                    u64 v7 = g_mask[(size_t)klist[i + 7] * NW + w];
                    acc |= ((v0 | v1) | (v2 | v3)) | ((v4 | v5) | (v6 | v7));
                }
                atomicOr(&remv[w], acc);
            }
        } else {
            // prefetch next chunk's diagonal block (threads 128..191)
            if (t < 192 && (c + 1) < Mw) {
                int r = (c + 1) * 64 + (t - 128);
                diag[buf ^ 1][t - 128] = (r < M) ? g_mask[(size_t)r * NW + (c + 1)] : 0ULL;
            }
            int w = t - 128;
            if (w > c && w < Mw && n16 > 0) {
                int half = n16 >> 1;
                u64 acc = 0ULL;
                for (int i = half; i < n16; i += 8) {
                    u64 v0 = g_mask[(size_t)klist[i + 0] * NW + w];
                    u64 v1 = g_mask[(size_t)klist[i + 1] * NW + w];
                    u64 v2 = g_mask[(size_t)klist[i + 2] * NW + w];
                    u64 v3 = g_mask[(size_t)klist[i + 3] * NW + w];
                    u64 v4 = g_mask[(size_t)klist[i + 4] * NW + w];
                    u64 v5 = g_mask[(size_t)klist[i + 5] * NW + w];
                    u64 v6 = g_mask[(size_t)klist[i + 6] * NW + w];
                    u64 v7 = g_mask[(size_t)klist[i + 7] * NW + w];
                    acc |= ((v0 | v1) | (v2 | v3)) | ((v4 | v5) | (v6 | v7));
                }
                atomicOr(&remv[w], acc);
            }
        }
        __syncthreads();                           // S2: remv + prefetch visible
    }
}

// ---------------- 6) write output: sorted boxes[:,1:5] * keep ----------------
__global__ void k_out(float4* __restrict__ out) {
    int i = blockIdx.x * blockDim.x + threadIdx.x;
    if (i >= NBOX) return;
    u64 kw = g_keep[i >> 6];
    float4 v = ((kw >> (i & 63)) & 1ULL) ? g_seph[i] : make_float4(0.f, 0.f, 0.f, 0.f);
    out[i] = v;
}

extern "C" void kernel_launch(void* const* d_in, const int* in_sizes, int n_in,
                              void* d_out, int out_size) {
    const float* in = (const float*)d_in[0];
    float4* out = (float4*)d_out;
    (void)in_sizes; (void)n_in; (void)out_size;

    k_prep       <<<64, 256>>>(in);
    k_hist       <<<64, 256>>>();
    k_suffix     <<<1, 1024>>>();
    k_bscatter   <<<64, 256>>>();
    k_rankscatter<<<64, 256>>>(in);
    k_mask       <<<dim3(256, 256), 64>>>();
    k_scan       <<<1, 256>>>();
    k_out        <<<64, 256>>>(out);
}

// round 7
// speedup vs baseline: 1.0086x; 1.0086x over previous
#include <cuda_runtime.h>

#define NBOX 16384
#define NW   256            // 64-bit words per mask row
#define NBKT 16384          // conf buckets for counting sort
#define CONF_THRESH 0.5f
#define PIOU_THRESH 0.5f

typedef unsigned long long u64;

// ---------------- device scratch (static; no allocation) ----------------
__device__ float4 g_seph[NBOX];                    // sorted [start,end,peak,height]
__device__ float  g_conf[NBOX];                    // dense confidence (unsorted)
__device__ int    g_hist[NBKT];                    // bucket histogram
__device__ int    g_off[NBKT];                     // #elements in buckets > b
__device__ int    g_cnt[NBKT];                     // scatter cursors
__device__ int    g_blist[NBOX];                   // bucket-grouped original indices
__device__ int    g_M;                             // count(conf > 0.5) == valid prefix len
__device__ u64    g_mask[(size_t)NBOX * NW];       // 32MB suppression bitmask
__device__ u64    g_keep[NW];                      // final keep bits (sorted order)

__device__ __forceinline__ int bucket_of(float c) {
    int b = (int)(c * 16384.0f);                   // exact pow2 mul; monotone
    return b > 16383 ? 16383 : b;
}

// ---------------- 1) gather conf, zero accumulators ----------------
__global__ void k_prep(const float* __restrict__ in) {
    int i = blockIdx.x * blockDim.x + threadIdx.x;
    if (i < NBOX) {
        g_conf[i] = in[i * 5 + 0];
        g_hist[i] = 0;
        g_cnt[i]  = 0;
    }
    if (i == 0) g_M = 0;
}

// ---------------- 2a) bucket histogram ----------------
__global__ void k_hist() {
    int i = blockIdx.x * blockDim.x + threadIdx.x;
    if (i < NBOX) atomicAdd(&g_hist[bucket_of(g_conf[i])], 1);
}

// ---------------- 2b) suffix sums: off[b] = #elements with bucket > b ----------
__global__ void k_suffix() {                       // 1 block, 1024 threads
    __shared__ int part[1024];
    int t = threadIdx.x;
    int base = t * 16;
    int v[16]; int s = 0;
#pragma unroll
    for (int k = 0; k < 16; k++) { v[k] = g_hist[base + k]; s += v[k]; }
    part[t] = s;
    __syncthreads();
    for (int off = 1; off < 1024; off <<= 1) {     // inclusive suffix scan of partials
        int x = (t + off < 1024) ? part[t + off] : 0;
        __syncthreads();
        part[t] += x;
        __syncthreads();
    }
    int above = part[t] - s;                       // sum of buckets >= (t+1)*16
    int o[16];
    o[15] = above;
#pragma unroll
    for (int k = 14; k >= 0; k--) o[k] = o[k + 1] + v[k + 1];
#pragma unroll
    for (int k = 0; k < 16; k++) g_off[base + k] = o[k];
}

// ---------------- 2c) scatter indices into bucket segments ----------------
__global__ void k_bscatter() {
    int i = blockIdx.x * blockDim.x + threadIdx.x;
    if (i >= NBOX) return;
    int b = bucket_of(g_conf[i]);
    int pos = g_off[b] + atomicAdd(&g_cnt[b], 1);
    g_blist[pos] = i;
}

// ---------------- 3) exact rank within bucket + scatter boxes ----------------
__global__ void k_rankscatter(const float* __restrict__ in) {
    int i = blockIdx.x * blockDim.x + threadIdx.x;
    if (i >= NBOX) return;
    float ci = g_conf[i];
    int b    = bucket_of(ci);
    int base = g_off[b], len = g_hist[b];
    int cnt = 0;
    for (int p = base; p < base + len; p++) {
        int j = g_blist[p];
        float cj = g_conf[j];
        cnt += (cj > ci) || (cj == ci && j < i);   // stable: (conf desc, idx asc)
    }
    int r = base + cnt;
    const float* row = in + (size_t)i * 5;
    g_seph[r] = make_float4(row[1], row[2], row[3], row[4]);
    if (ci > CONF_THRESH) atomicAdd(&g_M, 1);
}

// ---------------- 4) pairwise peak-IoU bitmask, upper-triangular blocks only ----
__global__ void k_mask() {
    __shared__ float4 cols[64];
    if (blockIdx.x < blockIdx.y) return;           // triangular: halves the work
    int M = g_M;
    if ((int)(blockIdx.y * 64) >= M) return;
    int j0 = blockIdx.x * 64;
    if (j0 >= M) return;
    int r = blockIdx.y * 64 + threadIdx.x;
    cols[threadIdx.x] = g_seph[j0 + threadIdx.x];
    __syncthreads();
    if (r >= M) return;
    float4 a = g_seph[r];
    float area1 = __fmul_rn(__fsub_rn(a.y, a.x), a.w);
    u64 w = 0;
#pragma unroll 4
    for (int k = 0; k < 64; k++) {
        float4 b = cols[k];
        float is = fmaxf(a.x, b.x);
        float ie = fminf(a.y, b.y);
        float il = __fsub_rn(ie, is);
        bool sup = false;
        if (il > 0.0f) {                           // piou>0 requires overlap
            float inter_h    = fminf(a.w, b.w);
            float inter_area = __fmul_rn(il, inter_h);
            float area2      = __fmul_rn(__fsub_rn(b.y, b.x), b.w);
            float union_area = __fsub_rn(__fadd_rn(area1, area2), inter_area);
            float iou        = __fdiv_rn(inter_area, union_area);
            float pd         = fabsf(__fsub_rn(a.z, b.z));
            float us         = fminf(a.x, b.x);
            float ue         = fmaxf(a.y, b.y);
            float ud         = fabsf(__fsub_rn(ue, us));
            float val        = __fsub_rn(iou, __fdiv_rn(pd, ud));
            sup = (val > PIOU_THRESH);
        }
        w |= ((u64)sup) << k;
    }
    int lim = M - j0;                              // mask invalid cols once
    if (lim < 64) w &= (1ULL << lim) - 1ULL;
    if (r >= j0 && r < j0 + 64) w &= ~(1ULL << (r - j0));   // self never suppresses
    g_mask[(size_t)r * NW + blockIdx.x] = w;
}

// ---------------- 5) greedy scan v5: warp-shuffle chain + 4-thread/word OR -----
// 512 threads. Warp 0: lane l holds diag words for bits l, l+32 in registers
// (prefetched via LDG each chunk). Chain runs redundantly on all 32 lanes with
// d[b] broadcast via shfl (independent of rm -> overlaps the ALU chain).
// klist built in parallel via popc. Phase C: 4 threads per word, 8 loads/batch.
__global__ void __launch_bounds__(512, 1) k_scan() {
    __shared__ u64 remv[NW];
    __shared__ int klist[96];
    __shared__ int nsh;
    int t = threadIdx.x;
    int lane = t & 31;
    if (t < NW) remv[t] = 0ULL;
    int M  = g_M;
    int Mw = (M + 63) >> 6;
    if (t >= Mw && t < NW) g_keep[t] = 0ULL;       // zero unused keep words

    u64 d_lo = 0ULL, d_hi = 0ULL;                  // diag regs (warp 0 only)
    if (t < 32) {
        if (lane      < M) d_lo = g_mask[(size_t)lane        * NW + 0];
        if (lane + 32 < M) d_hi = g_mask[(size_t)(lane + 32) * NW + 0];
    }
    __syncthreads();

    for (int c = 0; c < Mw; c++) {
        // ---- (B) warp-cooperative chain (warp 0, all lanes redundant) ----
        if (t < 32) {
            int lim   = M - (c << 6);
            u64 vmask = (lim >= 64) ? ~0ULL : ((1ULL << lim) - 1ULL);
            u64 rm    = remv[c] | ~vmask;          // invalid slots = pre-removed
            u64 kept  = 0ULL;
#pragma unroll
            for (int g = 0; g < 4; g++) {          // bits 0..31 from d_lo
                u64 v[8];
#pragma unroll
                for (int k = 0; k < 8; k++)
                    v[k] = __shfl_sync(0xffffffffu, d_lo, g * 8 + k);
#pragma unroll
                for (int k = 0; k < 8; k++) {
                    int b = g * 8 + k;
                    u64 m = ((rm >> b) & 1ULL) - 1ULL;  // ~0 keep, 0 removed
                    kept |= (1ULL << b) & m;
                    rm   |= v[k] & m;
                }
            }
#pragma unroll
            for (int g = 0; g < 4; g++) {          // bits 32..63 from d_hi
                u64 v[8];
#pragma unroll
                for (int k = 0; k < 8; k++)
                    v[k] = __shfl_sync(0xffffffffu, d_hi, g * 8 + k);
#pragma unroll
                for (int k = 0; k < 8; k++) {
                    int b = 32 + g * 8 + k;
                    u64 m = ((rm >> b) & 1ULL) - 1ULL;
                    kept |= (1ULL << b) & m;
                    rm   |= v[k] & m;
                }
            }
            // ---- parallel klist build (each lane handles bits lane, lane+32) ----
            int cbase = c << 6;
            int n = __popcll(kept);
            if ((kept >> lane) & 1ULL) {
                int pos = __popcll(kept & ((1ULL << lane) - 1ULL));
                klist[pos] = cbase + lane;
            }
            int l2 = lane + 32;
            if ((kept >> l2) & 1ULL) {
                int pos = (int)__popcll(kept & ((1ULL << l2) - 1ULL));
                klist[pos] = cbase + l2;
            }
            int n32 = (n + 31) & ~31;              // pad to mult of 32 (OR idempotent)
            if (n > 0) {
                int first = cbase + __ffsll((long long)kept) - 1;
                int idx = n + lane;
                if (idx < n32) klist[idx] = first;
            }
            if (lane == 0) {
                g_keep[c] = kept;
                nsh = n32;
            }
        }
        __syncthreads();                           // S1: klist/nsh visible
        int n32 = nsh;
        // ---- warp 0 prefetches next chunk's diag into registers ----
        if (t < 32 && (c + 1) < Mw) {
            int r0 = ((c + 1) << 6) + lane;
            int r1 = r0 + 32;
            d_lo = (r0 < M) ? g_mask[(size_t)r0 * NW + (c + 1)] : 0ULL;
            d_hi = (r1 < M) ? g_mask[(size_t)r1 * NW + (c + 1)] : 0ULL;
        }
        // ---- (C) OR kept rows into remv: 4 threads per word, 8 loads in flight --
        if (n32 > 0) {
            int sub = t & 3;
            for (int w = t >> 2; w < Mw; w += 128) {
                if (w > c) {
                    u64 acc = 0ULL;
                    for (int i = sub; i < n32; i += 32) {
                        u64 v0 = g_mask[(size_t)klist[i +  0] * NW + w];
                        u64 v1 = g_mask[(size_t)klist[i +  4] * NW + w];
                        u64 v2 = g_mask[(size_t)klist[i +  8] * NW + w];
                        u64 v3 = g_mask[(size_t)klist[i + 12] * NW + w];
                        u64 v4 = g_mask[(size_t)klist[i + 16] * NW + w];
                        u64 v5 = g_mask[(size_t)klist[i + 20] * NW + w];
                        u64 v6 = g_mask[(size_t)klist[i + 24] * NW + w];
                        u64 v7 = g_mask[(size_t)klist[i + 28] * NW + w];
                        acc |= ((v0 | v1) | (v2 | v3)) | ((v4 | v5) | (v6 | v7));
                    }
                    if (acc) atomicOr(&remv[w], acc);
                }
            }
        }
        __syncthreads();                           // S2: remv visible for next chain
    }
}

// ---------------- 6) write output: sorted boxes[:,1:5] * keep ----------------
__global__ void k_out(float4* __restrict__ out) {
    int i = blockIdx.x * blockDim.x + threadIdx.x;
    if (i >= NBOX) return;
    u64 kw = g_keep[i >> 6];
    float4 v = ((kw >> (i & 63)) & 1ULL) ? g_seph[i] : make_float4(0.f, 0.f, 0.f, 0.f);
    out[i] = v;
}

extern "C" void kernel_launch(void* const* d_in, const int* in_sizes, int n_in,
                              void* d_out, int out_size) {
    const float* in = (const float*)d_in[0];
    float4* out = (float4*)d_out;
    (void)in_sizes; (void)n_in; (void)out_size;

    k_prep       <<<64, 256>>>(in);
    k_hist       <<<64, 256>>>();
    k_suffix     <<<1, 1024>>>();
    k_bscatter   <<<64, 256>>>();
    k_rankscatter<<<64, 256>>>(in);
    k_mask       <<<dim3(256, 256), 64>>>();
    k_scan       <<<1, 512>>>();
    k_out        <<<64, 256>>>(out);
}

// round 9
// speedup vs baseline: 4.5987x; 4.5595x over previous
#include <cuda_runtime.h>

#define NBOX 16384
#define NW   256            // 64-bit words per mask row
#define NBKT 16384          // conf buckets for counting sort
#define NBLK 128            // persistent fixpoint CTAs (must be <= SM count)
#define CONF_THRESH 0.5f
#define PIOU_THRESH 0.5f

typedef unsigned long long u64;

// ---------------- device scratch (static; no allocation) ----------------
__device__ float4 g_seph[NBOX];                    // sorted [start,end,peak,height]
__device__ float  g_conf[NBOX];                    // dense confidence (unsorted)
__device__ int    g_hist[NBKT];                    // bucket histogram
__device__ int    g_off[NBKT];                     // #elements in buckets > b
__device__ int    g_cnt[NBKT];                     // scatter cursors
__device__ int    g_blist[NBOX];                   // bucket-grouped original indices
__device__ int    g_M;                             // count(conf > 0.5) == valid prefix len
__device__ u64    g_mask[(size_t)NBOX * NW];       // 32MB suppression bitmask
__device__ u64    g_P[NW];                         // possibly-kept bitmap (shrinks)
__device__ u64    g_D[NW];                         // definitely-kept bitmap (grows)
__device__ int    g_bar_count;                     // grid barrier ticket
__device__ int    g_bar_gen;                       // grid barrier generation
__device__ int    g_diff;                          // convergence flag (epoch-tagged)

__device__ __forceinline__ int bucket_of(float c) {
    int b = (int)(c * 16384.0f);                   // exact pow2 mul; monotone
    return b > 16383 ? 16383 : b;
}

// ---------------- 1) gather conf, zero accumulators ----------------
__global__ void k_prep(const float* __restrict__ in) {
    int i = blockIdx.x * blockDim.x + threadIdx.x;
    if (i < NBOX) {
        g_conf[i] = in[i * 5 + 0];
        g_hist[i] = 0;
        g_cnt[i]  = 0;
    }
    if (i == 0) g_M = 0;
}

// ---------------- 2a) bucket histogram ----------------
__global__ void k_hist() {
    int i = blockIdx.x * blockDim.x + threadIdx.x;
    if (i < NBOX) atomicAdd(&g_hist[bucket_of(g_conf[i])], 1);
}

// ---------------- 2b) suffix sums: off[b] = #elements with bucket > b ----------
__global__ void k_suffix() {                       // 1 block, 1024 threads
    __shared__ int part[1024];
    int t = threadIdx.x;
    int base = t * 16;
    int v[16]; int s = 0;
#pragma unroll
    for (int k = 0; k < 16; k++) { v[k] = g_hist[base + k]; s += v[k]; }
    part[t] = s;
    __syncthreads();
    for (int off = 1; off < 1024; off <<= 1) {     // inclusive suffix scan of partials
        int x = (t + off < 1024) ? part[t + off] : 0;
        __syncthreads();
        part[t] += x;
        __syncthreads();
    }
    int above = part[t] - s;                       // sum of buckets >= (t+1)*16
    int o[16];
    o[15] = above;
#pragma unroll
    for (int k = 14; k >= 0; k--) o[k] = o[k + 1] + v[k + 1];
#pragma unroll
    for (int k = 0; k < 16; k++) g_off[base + k] = o[k];
}

// ---------------- 2c) scatter indices into bucket segments ----------------
__global__ void k_bscatter() {
    int i = blockIdx.x * blockDim.x + threadIdx.x;
    if (i >= NBOX) return;
    int b = bucket_of(g_conf[i]);
    int pos = g_off[b] + atomicAdd(&g_cnt[b], 1);
    g_blist[pos] = i;
}

// ---------------- 3) exact rank within bucket + scatter boxes ----------------
__global__ void k_rankscatter(const float* __restrict__ in) {
    int i = blockIdx.x * blockDim.x + threadIdx.x;
    if (i >= NBOX) return;
    float ci = g_conf[i];
    int b    = bucket_of(ci);
    int base = g_off[b], len = g_hist[b];
    int cnt = 0;
    for (int p = base; p < base + len; p++) {
        int j = g_blist[p];
        float cj = g_conf[j];
        cnt += (cj > ci) || (cj == ci && j < i);   // stable: (conf desc, idx asc)
    }
    int r = base + cnt;
    const float* row = in + (size_t)i * 5;
    g_seph[r] = make_float4(row[1], row[2], row[3], row[4]);
    if (ci > CONF_THRESH) atomicAdd(&g_M, 1);
}

// ---------------- 4) pairwise peak-IoU bitmask, upper-triangular blocks only ----
// Mask is symmetric in value; we store row r's words for blocks bx >= by only.
__global__ void k_mask() {
    __shared__ float4 cols[64];
    if (blockIdx.x < blockIdx.y) return;           // triangular: halves the work
    int M = g_M;
    if ((int)(blockIdx.y * 64) >= M) return;
    int j0 = blockIdx.x * 64;
    if (j0 >= M) return;
    int r = blockIdx.y * 64 + threadIdx.x;
    cols[threadIdx.x] = g_seph[j0 + threadIdx.x];
    __syncthreads();
    if (r >= M) return;
    float4 a = g_seph[r];
    float area1 = __fmul_rn(__fsub_rn(a.y, a.x), a.w);
    u64 w = 0;
#pragma unroll 4
    for (int k = 0; k < 64; k++) {
        float4 b = cols[k];
        float is = fmaxf(a.x, b.x);
        float ie = fminf(a.y, b.y);
        float il = __fsub_rn(ie, is);
        bool sup = false;
        if (il > 0.0f) {                           // piou>0 requires overlap
            float inter_h    = fminf(a.w, b.w);
            float inter_area = __fmul_rn(il, inter_h);
            float area2      = __fmul_rn(__fsub_rn(b.y, b.x), b.w);
            float union_area = __fsub_rn(__fadd_rn(area1, area2), inter_area);
            float iou        = __fdiv_rn(inter_area, union_area);
            float pd         = fabsf(__fsub_rn(a.z, b.z));
            float us         = fminf(a.x, b.x);
            float ue         = fmaxf(a.y, b.y);
            float ud         = fabsf(__fsub_rn(ue, us));
            float val        = __fsub_rn(iou, __fdiv_rn(pd, ud));
            sup = (val > PIOU_THRESH);
        }
        w |= ((u64)sup) << k;
    }
    int lim = M - j0;                              // mask invalid cols once
    if (lim < 64) w &= (1ULL << lim) - 1ULL;
    if (r >= j0 && r < j0 + 64) w &= ~(1ULL << (r - j0));   // self never suppresses
    g_mask[(size_t)r * NW + blockIdx.x] = w;
}

// ---------------- 5) persistent fixpoint NMS ----------------
// D/P two-sided monotone iteration converging to the exact greedy keep set.
// 128 co-resident CTAs x 256 threads, software grid barrier.

__device__ __forceinline__ void gridsync(int& gen) {
    __syncthreads();
    if (threadIdx.x == 0) {
        __threadfence();                           // publish our writes (CCTL.IVALL)
        if (atomicAdd(&g_bar_count, 1) == NBLK - 1) {
            g_bar_count = 0;
            __threadfence();
            atomicExch(&g_bar_gen, gen + 1);       // release
        } else {
            while (atomicAdd(&g_bar_gen, 0) <= gen) { }
        }
        gen++;
        __threadfence();                           // acquire: invalidate stale L1
    }
    __syncthreads();
}

// Per-thread partial suppression word for target word w from set-bitmap sb:
// OR of mask[j][w] over set rows j < min(M, 64(w+1)), diag word trimmed to j<i.
__device__ __forceinline__ u64 sweep_partial(const u64* __restrict__ sb, int w, int M) {
    int hi = (w + 1) << 6;
    if (hi > M) hi = M;
    int wtop = w << 6;
    u64 acc = 0ULL;
    for (int j = threadIdx.x; j < hi; j += 256) {
        if ((sb[j >> 6] >> (j & 63)) & 1ULL) {
            u64 v = g_mask[(size_t)j * NW + w];
            if (j >= wtop) {                       // diagonal chunk: bits > bj only
                int bj = j & 63;
                v = (bj == 63) ? 0ULL : (v & (~0ULL << (bj + 1)));
            }
            acc |= v;
        }
    }
    return acc;
}

__device__ __forceinline__ u64 block_or(u64 v, u64* s_acc) {
#pragma unroll
    for (int o = 16; o > 0; o >>= 1)
        v |= __shfl_down_sync(0xffffffffu, v, o);
    if ((threadIdx.x & 31) == 0) s_acc[threadIdx.x >> 5] = v;
    __syncthreads();
    u64 r = 0ULL;
    if (threadIdx.x == 0) {
#pragma unroll
        for (int k = 0; k < 8; k++) r |= s_acc[k];
    }
    return r;                                      // valid on thread 0 only
}

__global__ void __launch_bounds__(256, 1) k_fix(float4* __restrict__ out) {
    __shared__ u64 s_bits[NW];
    __shared__ u64 s_acc[8];
    __shared__ int s_cont;
    int tid  = threadIdx.x;
    int bid  = blockIdx.x;
    int gtid = bid * 256 + tid;                    // 0..32767
    int gen = 0;
    if (tid == 0) gen = atomicAdd(&g_bar_gen, 0);  // replay-safe baseline
    int M  = g_M;
    int Mw = (M + 63) >> 6;

    // init: P = valid prefix, D = 0
    if (gtid < NW) {
        int lim = M - (gtid << 6);
        u64 vm = (lim >= 64) ? ~0ULL : ((lim <= 0) ? 0ULL : ((1ULL << lim) - 1ULL));
        g_P[gtid] = vm;
        g_D[gtid] = 0ULL;
    }
    if (gtid == 0) g_diff = 0;
    gridsync(gen);

    for (int it = 0;; it++) {
        // ---- Phase A: D = valid & ~suppr(P) ----
        if (tid < NW) s_bits[tid] = g_P[tid];
        __syncthreads();
        for (int w = bid; w < Mw; w += NBLK) {
            u64 sup = sweep_partial(s_bits, w, M);
            sup = block_or(sup, s_acc);
            if (tid == 0) {
                int lim = M - (w << 6);
                u64 vm = (lim >= 64) ? ~0ULL : ((1ULL << lim) - 1ULL);
                g_D[w] = vm & ~sup;
            }
            __syncthreads();                       // s_acc reuse
        }
        gridsync(gen);
        // ---- Phase B: Pnew = valid & ~suppr(D); converged iff Pnew == D ----
        if (tid < NW) s_bits[tid] = g_D[tid];
        __syncthreads();
        for (int w = bid; w < Mw; w += NBLK) {
            u64 sup = sweep_partial(s_bits, w, M);
            sup = block_or(sup, s_acc);
            if (tid == 0) {
                int lim = M - (w << 6);
                u64 vm = (lim >= 64) ? ~0ULL : ((1ULL << lim) - 1ULL);
                u64 pn = vm & ~sup;
                g_P[w] = pn;
                if (pn != s_bits[w]) atomicMax(&g_diff, it + 1);
            }
            __syncthreads();
        }
        gridsync(gen);
        // ---- Phase C: uniform convergence decision (reads only) ----
        if (tid == 0) s_cont = (atomicAdd(&g_diff, 0) > it);
        __syncthreads();
        if (!s_cont) break;
        // no sync needed C->A: A rewrites g_D, which nothing reads until after
        // the A->B barrier; g_P stable until B which is also barrier-protected.
    }

    // ---- output: keep == D (== P at fixpoint) ----
    if (gtid < NBOX) {
        u64 kw = g_D[gtid >> 6];
        float4 v = ((kw >> (gtid & 63)) & 1ULL) ? g_seph[gtid]
                                                : make_float4(0.f, 0.f, 0.f, 0.f);
        out[gtid] = v;
    }
}

extern "C" void kernel_launch(void* const* d_in, const int* in_sizes, int n_in,
                              void* d_out, int out_size) {
    const float* in = (const float*)d_in[0];
    float4* out = (float4*)d_out;
    (void)in_sizes; (void)n_in; (void)out_size;

    k_prep       <<<64, 256>>>(in);
    k_hist       <<<64, 256>>>();
    k_suffix     <<<1, 1024>>>();
    k_bscatter   <<<64, 256>>>();
    k_rankscatter<<<64, 256>>>(in);
    k_mask       <<<dim3(256, 256), 64>>>();
    k_fix        <<<NBLK, 256>>>(out);
}